// round 7
// baseline (speedup 1.0000x reference)
#include <cuda_runtime.h>

// LearnedClassVectors: HU bucketize (10 bins) -> 12-dim embedding gather ->
// 4x4x4 patch unfold -> channel-major output (2, 768, 32, 32, 32) fp32.
//
//   x:       (2,1,128,128,128) fp32   d_in[0]
//   vectors: (10,12)           fp32   d_in[1]
//   out:     (2,768,32,32,32)  fp32   50,331,648 elements
//
// R4 design changes vs R3 (34.8us kernel, DRAM 57.8%, L1 60%):
//   - gather embedding rows as float4 (3 x LDS.128/row) instead of 12 scalar
//     LDS.32: 192 -> 48 shared loads per thread
//   - 2 w-tiles per thread -> 512 blocks -> single full wave (no 73% tail wave)
//   - v-quad chunking keeps <=16 staged floats live -> lower regs, higher occ
//   - __ldcs / __stcs streaming hints (zero-reuse streams)

static __device__ __forceinline__ int hu_bin(float v) {
    // searchsorted(edges, v, side='right') == count of edges <= v
    int b = 0;
    b += (v >= -1000.0f);
    b += (v >=   -75.0f);
    b += (v >=     0.0f);
    b += (v >=    15.0f);
    b += (v >=    25.0f);
    b += (v >=    40.0f);
    b += (v >=    50.0f);
    b += (v >=   200.0f);
    b += (v >=  1000.0f);
    return b;
}

__global__ __launch_bounds__(256)
void lcv_kernel(const float* __restrict__ x,
                const float* __restrict__ vectors,
                float* __restrict__ out) {
    // 10 rows x 12 floats; each row = 3 aligned float4
    __shared__ __align__(16) float s_vec[10 * 12];
    if (threadIdx.x < 120) s_vec[threadIdx.x] = vectors[threadIdx.x];
    __syncthreads();
    const float4* s4 = (const float4*)s_vec;

    unsigned tid = blockIdx.x * blockDim.x + threadIdx.x;   // 0 .. 131071
    int twh = tid & 3;           // w-tile pair id: tiles twh and twh+4
    unsigned r = tid >> 2;
    int h = r & 127; r >>= 7;
    int d = r & 127; r >>= 7;
    int b = (int)r;              // 0..1

    int gd = d >> 2, pd = d & 3;
    int gh = h >> 2, ph = h & 3;

    const float* xrow = x + (size_t)((b * 128 + d) * 128 + h) * 128;
    float* ob0 = out + (size_t)b * (768u * 32768u)
                     + (unsigned)gd * 1024u + (unsigned)gh * 32u;
    int chbase = (pd * 16 + ph * 4) * 12;   // + pw*12 + v

#pragma unroll
    for (int t = 0; t < 2; t++) {
        int tw = twh + 4 * t;    // this tile covers w = 16*tw .. 16*tw+15

        // ---- 16 consecutive x values (4x LDG.128, streaming) ----
        const float4* xp = (const float4*)(xrow + (unsigned)tw * 16u);
        float4 xv0 = __ldcs(xp + 0);
        float4 xv1 = __ldcs(xp + 1);
        float4 xv2 = __ldcs(xp + 2);
        float4 xv3 = __ldcs(xp + 3);

        // pack 4 gw-bins per pw into one int (byte lanes g=0..3)
        int bpp[4];
        bpp[0] = hu_bin(xv0.x) | (hu_bin(xv1.x) << 8) | (hu_bin(xv2.x) << 16) | (hu_bin(xv3.x) << 24);
        bpp[1] = hu_bin(xv0.y) | (hu_bin(xv1.y) << 8) | (hu_bin(xv2.y) << 16) | (hu_bin(xv3.y) << 24);
        bpp[2] = hu_bin(xv0.z) | (hu_bin(xv1.z) << 8) | (hu_bin(xv2.z) << 16) | (hu_bin(xv3.z) << 24);
        bpp[3] = hu_bin(xv0.w) | (hu_bin(xv1.w) << 8) | (hu_bin(xv2.w) << 16) | (hu_bin(xv3.w) << 24);

        float* obt = ob0 + (unsigned)tw * 4u;

#pragma unroll
        for (int pw = 0; pw < 4; pw++) {
            int bp = bpp[pw];
            const float4* q0 = s4 + (bp & 15)         * 3;
            const float4* q1 = s4 + ((bp >> 8) & 15)  * 3;
            const float4* q2 = s4 + ((bp >> 16) & 15) * 3;
            const float4* q3 = s4 + ((bp >> 24) & 15) * 3;

            float* op = obt + (size_t)(chbase + pw * 12) * 32768u;
#pragma unroll
            for (int vc = 0; vc < 3; vc++) {
                // 4 LDS.128: full embedding rows for the 4 gw voxels
                float4 c0 = q0[vc], c1 = q1[vc], c2 = q2[vc], c3 = q3[vc];
                // transpose in regs -> 4 STG.128, one channel each
                __stcs((float4*)(op          ), make_float4(c0.x, c1.x, c2.x, c3.x));
                __stcs((float4*)(op + 32768u ), make_float4(c0.y, c1.y, c2.y, c3.y));
                __stcs((float4*)(op + 65536u ), make_float4(c0.z, c1.z, c2.z, c3.z));
                __stcs((float4*)(op + 98304u ), make_float4(c0.w, c1.w, c2.w, c3.w));
                op += 4u * 32768u;
            }
        }
    }
}

extern "C" void kernel_launch(void* const* d_in, const int* in_sizes, int n_in,
                              void* d_out, int out_size) {
    const float* x       = (const float*)d_in[0];
    const float* vectors = (const float*)d_in[1];
    float* out           = (float*)d_out;

    // 131072 threads, 2 w-tiles each: 512 blocks -> single wave on 148 SMs
    lcv_kernel<<<512, 256>>>(x, vectors, out);
}

// round 10
// speedup vs baseline: 1.1076x; 1.1076x over previous
#include <cuda_runtime.h>

// LearnedClassVectors: HU bucketize (10 bins) -> 12-dim embedding gather ->
// 4x4x4 patch unfold -> channel-major output (2, 768, 32, 32, 32) fp32.
//
//   x:       (2,1,128,128,128) fp32   d_in[0]
//   vectors: (10,12)           fp32   d_in[1]
//   out:     (2,768,32,32,32)  fp32   50,331,648 elements
//
// R7 = R3 warp mapping (tw = tid&7 -> each STG.128 covers 4 full 128B
// segments per warp; this is what R4 broke) + float4 table gather chunked
// by v-quad (48 LDS.128 instead of 192 LDS.32, <=16 staged floats live)
// + reg cap for 5 blocks/SM occupancy.

static __device__ __forceinline__ int hu_bin(float v) {
    // searchsorted(edges, v, side='right') == count of edges <= v
    int b = 0;
    b += (v >= -1000.0f);
    b += (v >=   -75.0f);
    b += (v >=     0.0f);
    b += (v >=    15.0f);
    b += (v >=    25.0f);
    b += (v >=    40.0f);
    b += (v >=    50.0f);
    b += (v >=   200.0f);
    b += (v >=  1000.0f);
    return b;
}

__global__ __launch_bounds__(256, 5)
void lcv_kernel(const float* __restrict__ x,
                const float* __restrict__ vectors,
                float* __restrict__ out) {
    // 10 rows x 12 floats; each row = 3 aligned float4
    __shared__ __align__(16) float s_vec[10 * 12];
    if (threadIdx.x < 120) s_vec[threadIdx.x] = vectors[threadIdx.x];
    __syncthreads();
    const float4* s4 = (const float4*)s_vec;

    unsigned tid = blockIdx.x * blockDim.x + threadIdx.x;   // 0 .. 262143
    int tw = tid & 7;            // w-tile: covers w = 16*tw .. 16*tw+15
    unsigned r = tid >> 3;
    int h = r & 127; r >>= 7;
    int d = r & 127; r >>= 7;
    int b = (int)r;              // 0..1

    // ---- 16 consecutive x values (4x LDG.128) ----
    const float4* xp = (const float4*)(x +
        ((size_t)((b * 128 + d) * 128 + h) * 128 + (unsigned)tw * 16u));
    float4 xv0 = xp[0];
    float4 xv1 = xp[1];
    float4 xv2 = xp[2];
    float4 xv3 = xp[3];

    // pack the 4 gw-bins for each pw into one int (nibble lanes g=0..3)
    int bpp[4];
    bpp[0] = hu_bin(xv0.x) | (hu_bin(xv1.x) << 8) | (hu_bin(xv2.x) << 16) | (hu_bin(xv3.x) << 24);
    bpp[1] = hu_bin(xv0.y) | (hu_bin(xv1.y) << 8) | (hu_bin(xv2.y) << 16) | (hu_bin(xv3.y) << 24);
    bpp[2] = hu_bin(xv0.z) | (hu_bin(xv1.z) << 8) | (hu_bin(xv2.z) << 16) | (hu_bin(xv3.z) << 24);
    bpp[3] = hu_bin(xv0.w) | (hu_bin(xv1.w) << 8) | (hu_bin(xv2.w) << 16) | (hu_bin(xv3.w) << 24);

    // ---- output addressing ----
    int gd = d >> 2, pd = d & 3;
    int gh = h >> 2, ph = h & 3;
    float* ob = out + (size_t)b * (768u * 32768u)
                    + (unsigned)gd * 1024u + (unsigned)gh * 32u
                    + (unsigned)tw * 4u;
    int chbase = (pd * 16 + ph * 4) * 12;   // + pw*12 + v

#pragma unroll
    for (int pw = 0; pw < 4; pw++) {
        int bp = bpp[pw];
        const float4* q0 = s4 + (bp & 15)         * 3;
        const float4* q1 = s4 + ((bp >> 8) & 15)  * 3;
        const float4* q2 = s4 + ((bp >> 16) & 15) * 3;
        const float4* q3 = s4 + ((bp >> 24) & 15) * 3;

        float* op = ob + (size_t)(chbase + pw * 12) * 32768u;
#pragma unroll
        for (int vc = 0; vc < 3; vc++) {
            // 4x LDS.128: one v-quad of the embedding row for each gw voxel
            float4 c0 = q0[vc], c1 = q1[vc], c2 = q2[vc], c3 = q3[vc];
            // transpose in regs -> 4x STG.128; warp lanes 0..7 (tw=0..7)
            // pack each store into a full 128B segment
            *(float4*)(op          ) = make_float4(c0.x, c1.x, c2.x, c3.x);
            *(float4*)(op + 32768u ) = make_float4(c0.y, c1.y, c2.y, c3.y);
            *(float4*)(op + 65536u ) = make_float4(c0.z, c1.z, c2.z, c3.z);
            *(float4*)(op + 98304u ) = make_float4(c0.w, c1.w, c2.w, c3.w);
            op += 4u * 32768u;
        }
    }
}

extern "C" void kernel_launch(void* const* d_in, const int* in_sizes, int n_in,
                              void* d_out, int out_size) {
    const float* x       = (const float*)d_in[0];
    const float* vectors = (const float*)d_in[1];
    float* out           = (float*)d_out;

    // 262144 threads, one 16-voxel w-tile each: 1024 blocks
    lcv_kernel<<<1024, 256>>>(x, vectors, out);
}